// round 4
// baseline (speedup 1.0000x reference)
#include <cuda_runtime.h>
#include <cstdint>

#define BATCH 8
#define CDIM  128
#define NHEAD 4
#define HDIM  32
#define NQ    4096
#define QT    128          // q rows per CTA
#define KTILE 64           // keys per tile
#define NKT   (NQ / KTILE) // 64
#define KP    36           // K smem pitch (floats)  -> conflict-free B-frag loads
#define VP    40           // V smem pitch (floats)  -> conflict-free B-frag loads
#define PP    36           // P smem pitch (floats)  -> conflict-free A-frag loads
#define ATTN_SMEM_FLOATS (2*KTILE*KP + 2*KTILE*VP + 4*32*PP)   // 14336 -> 57344 B

// Scratch (allocation-free rule: __device__ globals)
__device__ float g_Q[(size_t)BATCH * NHEAD * NQ * HDIM];   // [b][h][n][d] pre-scaled tf32
__device__ float g_K[(size_t)BATCH * NHEAD * NQ * HDIM];   // [b][h][n][d] tf32
__device__ float g_V[(size_t)BATCH * NHEAD * NQ * HDIM];   // [b][h][n][d] tf32
__device__ float g_O[(size_t)BATCH * CDIM * NQ];           // [b][e][n] channel-major f32

// ---------------- helpers ----------------
__device__ __forceinline__ unsigned long long pk2(float lo, float hi) {
    unsigned long long r;
    asm("mov.b64 %0, {%1, %2};" : "=l"(r) : "f"(lo), "f"(hi));
    return r;
}
__device__ __forceinline__ float2 upk(unsigned long long v) {
    float2 f;
    asm("mov.b64 {%0, %1}, %2;" : "=f"(f.x), "=f"(f.y) : "l"(v));
    return f;
}
__device__ __forceinline__ void fma2(unsigned long long& d, unsigned long long a, unsigned long long b) {
    asm("fma.rn.f32x2 %0, %1, %2, %0;" : "+l"(d) : "l"(a), "l"(b));
}
__device__ __forceinline__ float ex2(float x) {
    float r;
    asm("ex2.approx.f32 %0, %1;" : "=f"(r) : "f"(x));
    return r;
}
__device__ __forceinline__ uint32_t tf32r(float f) {   // round f32 -> tf32 bits (f32 layout)
    uint32_t u;
    asm("cvt.rna.tf32.f32 %0, %1;" : "=r"(u) : "f"(f));
    return u;
}
__device__ __forceinline__ uint32_t smem_u32(const void* p) {
    uint32_t a;
    asm("{ .reg .u64 t; cvta.to.shared.u64 t, %1; cvt.u32.u64 %0, t; }" : "=r"(a) : "l"(p));
    return a;
}
__device__ __forceinline__ void cpa16(uint32_t dst, const void* src) {
    asm volatile("cp.async.cg.shared.global [%0], [%1], 16;" :: "r"(dst), "l"(src));
}
#define CP_COMMIT() asm volatile("cp.async.commit_group;" ::: "memory")
#define CP_WAIT(n)  asm volatile("cp.async.wait_group %0;" :: "n"(n) : "memory")

// m16n8k8 tf32 MMA (Ampere-compatible, no 'a'-target features)
__device__ __forceinline__ void mma1688(float* c, const uint32_t* a, const uint32_t* b) {
    asm volatile("mma.sync.aligned.m16n8k8.row.col.f32.tf32.tf32.f32 "
        "{%0,%1,%2,%3}, {%4,%5,%6,%7}, {%8,%9}, {%0,%1,%2,%3};"
        : "+f"(c[0]), "+f"(c[1]), "+f"(c[2]), "+f"(c[3])
        : "r"(a[0]), "r"(a[1]), "r"(a[2]), "r"(a[3]), "r"(b[0]), "r"(b[1]));
}

#define SCALE_LOG2E 0.25506770310758727f   // (1/sqrt(32)) * log2(e)

// =====================================================================
// Projection GEMM.   Out[e][n] = sum_c W[e][c]*X[b][c][n] + bias[e]
// mode 0: write [b][e][n] plain f32 (final output / attention input O)
// mode 1: write [b][h][n][d], tf32-rounded           (K, V)
// mode 2: write [b][h][n][d], *SCALE_LOG2E, tf32-rounded (Q)
// =====================================================================
__global__ __launch_bounds__(256)
void gemm_proj(const float* __restrict__ X, const float* __restrict__ Wt,
               const float* __restrict__ bias, float* __restrict__ Out,
               int mode)
{
    __shared__ __align__(16) float Ws[32][132];
    __shared__ __align__(16) float Xs[32][68];

    const int b   = blockIdx.y;
    const int n0  = blockIdx.x * 64;
    const int tid = threadIdx.x;
    const int e0  = (tid >> 4) * 8;
    const int nn0 = (tid & 15) * 4;
    const float* Xb = X + (size_t)b * CDIM * NQ;

    unsigned long long acc2[4][4];
#pragma unroll
    for (int i = 0; i < 4; ++i)
#pragma unroll
        for (int j = 0; j < 4; ++j) acc2[i][j] = 0ULL;

    for (int kt = 0; kt < 4; ++kt) {
        const int k0 = kt * 32;
        {
            const int cc = (tid & 7) * 4;
#pragma unroll
            for (int pass = 0; pass < 4; ++pass) {
                const int e = (tid >> 3) + pass * 32;
                const float4 w4 = *(const float4*)&Wt[e * CDIM + k0 + cc];
                Ws[cc + 0][e] = w4.x; Ws[cc + 1][e] = w4.y;
                Ws[cc + 2][e] = w4.z; Ws[cc + 3][e] = w4.w;
            }
        }
        {
            const int nn = (tid & 15) * 4;
#pragma unroll
            for (int pass = 0; pass < 2; ++pass) {
                const int kk = (tid >> 4) + pass * 16;
                *(float4*)&Xs[kk][nn] =
                    *(const float4*)&Xb[(size_t)(k0 + kk) * NQ + n0 + nn];
            }
        }
        __syncthreads();

#pragma unroll 8
        for (int kk = 0; kk < 32; ++kk) {
            const ulonglong2 wA = *(const ulonglong2*)&Ws[kk][e0];
            const ulonglong2 wB = *(const ulonglong2*)&Ws[kk][e0 + 4];
            const float4 xv = *(const float4*)&Xs[kk][nn0];
            unsigned long long xb;
            xb = pk2(xv.x, xv.x);
            fma2(acc2[0][0], wA.x, xb); fma2(acc2[1][0], wA.y, xb);
            fma2(acc2[2][0], wB.x, xb); fma2(acc2[3][0], wB.y, xb);
            xb = pk2(xv.y, xv.y);
            fma2(acc2[0][1], wA.x, xb); fma2(acc2[1][1], wA.y, xb);
            fma2(acc2[2][1], wB.x, xb); fma2(acc2[3][1], wB.y, xb);
            xb = pk2(xv.z, xv.z);
            fma2(acc2[0][2], wA.x, xb); fma2(acc2[1][2], wA.y, xb);
            fma2(acc2[2][2], wB.x, xb); fma2(acc2[3][2], wB.y, xb);
            xb = pk2(xv.w, xv.w);
            fma2(acc2[0][3], wA.x, xb); fma2(acc2[1][3], wA.y, xb);
            fma2(acc2[2][3], wB.x, xb); fma2(acc2[3][3], wB.y, xb);
        }
        __syncthreads();
    }

    const float4 bl = *(const float4*)&bias[e0];
    const float4 bh = *(const float4*)&bias[e0 + 4];

    if (mode >= 1) {
        const float mul = (mode == 2) ? SCALE_LOG2E : 1.0f;
        const int h  = e0 >> 5;
        const int d0 = e0 & 31;
        float* base = Out + ((size_t)(b * NHEAD + h) * NQ) * HDIM + d0;
#pragma unroll
        for (int j = 0; j < 4; ++j) {
            const int n = n0 + nn0 + j;
            const float2 p0 = upk(acc2[0][j]);
            const float2 p1 = upk(acc2[1][j]);
            const float2 p2 = upk(acc2[2][j]);
            const float2 p3 = upk(acc2[3][j]);
            float4 lo = make_float4(p0.x + bl.x, p0.y + bl.y, p1.x + bl.z, p1.y + bl.w);
            float4 hi = make_float4(p2.x + bh.x, p2.y + bh.y, p3.x + bh.z, p3.y + bh.w);
            lo.x = __uint_as_float(tf32r(lo.x * mul));
            lo.y = __uint_as_float(tf32r(lo.y * mul));
            lo.z = __uint_as_float(tf32r(lo.z * mul));
            lo.w = __uint_as_float(tf32r(lo.w * mul));
            hi.x = __uint_as_float(tf32r(hi.x * mul));
            hi.y = __uint_as_float(tf32r(hi.y * mul));
            hi.z = __uint_as_float(tf32r(hi.z * mul));
            hi.w = __uint_as_float(tf32r(hi.w * mul));
            *(float4*)&base[(size_t)n * HDIM]     = lo;
            *(float4*)&base[(size_t)n * HDIM + 4] = hi;
        }
    } else {
#pragma unroll
        for (int i = 0; i < 8; ++i) {
            float vals[4];
#pragma unroll
            for (int j = 0; j < 4; ++j) {
                const float2 pp = upk(acc2[i >> 1][j]);
                vals[j] = (i & 1) ? pp.y : pp.x;
            }
            const float bi = (i == 0) ? bl.x : (i == 1) ? bl.y : (i == 2) ? bl.z : (i == 3) ? bl.w
                           : (i == 4) ? bh.x : (i == 5) ? bh.y : (i == 6) ? bh.z : bh.w;
            const float4 st = make_float4(vals[0] + bi, vals[1] + bi, vals[2] + bi, vals[3] + bi);
            *(float4*)&Out[((size_t)b * CDIM + e0 + i) * NQ + n0 + nn0] = st;
        }
    }
}

// =====================================================================
// Flash attention on mma.sync (tf32), 128 threads / 4 warps per CTA.
// CTA = 128 q-rows of one (b,h); warp w owns rows [w*32, w*32+32).
// Per key-tile (64 keys): GEMM1 S=Q@K^T (regs), exp2, P->smem (warp-
// private), GEMM2 O+=P@V. Max-free softmax (bounded logits), O
// accumulated unscaled in registers; epilogue divides by row sum.
// K/V double-buffered via cp.async.
// =====================================================================
__global__ __launch_bounds__(128)
void attn_mma()
{
    extern __shared__ float smf[];
    float* Ks = smf;                            // [2][KTILE][KP]
    float* Vs = smf + 2 * KTILE * KP;           // [2][KTILE][VP]
    float* Ps = smf + 2 * KTILE * KP + 2 * KTILE * VP;  // [4][32][PP]

    const int qt = blockIdx.x, h = blockIdx.y, b = blockIdx.z;
    const int tid = threadIdx.x;
    const int w = tid >> 5, lane = tid & 31;
    const int g = lane >> 2, m4 = lane & 3;

    const float* Qg = g_Q + ((size_t)(b * NHEAD + h) * NQ + (size_t)qt * QT) * HDIM;
    const float* Kg = g_K + (size_t)(b * NHEAD + h) * NQ * HDIM;
    const float* Vg = g_V + (size_t)(b * NHEAD + h) * NQ * HDIM;

    // ---- Q A-fragments: loaded once, live all kernel ----
    uint32_t qa[2][4][4];
#pragma unroll
    for (int mb = 0; mb < 2; ++mb)
#pragma unroll
        for (int kb = 0; kb < 4; ++kb) {
            const int r0 = w * 32 + mb * 16 + g;
            const int c0 = kb * 8 + m4;
            qa[mb][kb][0] = __float_as_uint(Qg[(size_t)r0 * HDIM + c0]);
            qa[mb][kb][1] = __float_as_uint(Qg[(size_t)(r0 + 8) * HDIM + c0]);
            qa[mb][kb][2] = __float_as_uint(Qg[(size_t)r0 * HDIM + c0 + 4]);
            qa[mb][kb][3] = __float_as_uint(Qg[(size_t)(r0 + 8) * HDIM + c0 + 4]);
        }

    float oc[2][4][4];
#pragma unroll
    for (int mb = 0; mb < 2; ++mb)
#pragma unroll
        for (int nb = 0; nb < 4; ++nb)
#pragma unroll
            for (int i = 0; i < 4; ++i) oc[mb][nb][i] = 0.0f;
    float ls[2][2] = {{0.0f, 0.0f}, {0.0f, 0.0f}};

    const uint32_t ks_b = smem_u32(Ks);
    const uint32_t vs_b = smem_u32(Vs);

    auto load_tile = [&](int kt, int buf) {
#pragma unroll
        for (int i = 0; i < 4; ++i) {
            const int c = tid + i * 128;               // 512 16B chunks
            const int key = c >> 3, q16 = c & 7;
            cpa16(ks_b + (uint32_t)((buf * KTILE * KP + key * KP + q16 * 4) * 4),
                  Kg + (size_t)(kt * KTILE + key) * HDIM + q16 * 4);
        }
#pragma unroll
        for (int i = 0; i < 4; ++i) {
            const int c = tid + i * 128;
            const int key = c >> 3, q16 = c & 7;
            cpa16(vs_b + (uint32_t)((buf * KTILE * VP + key * VP + q16 * 4) * 4),
                  Vg + (size_t)(kt * KTILE + key) * HDIM + q16 * 4);
        }
    };

    load_tile(0, 0); CP_COMMIT();
    float* Pw = Ps + w * 32 * PP;

    for (int kt = 0; kt < NKT; ++kt) {
        const int buf = kt & 1;
        if (kt + 1 < NKT) { load_tile(kt + 1, buf ^ 1); CP_COMMIT(); CP_WAIT(1); }
        else              { CP_WAIT(0); }
        __syncthreads();

        const float* Kt = Ks + buf * KTILE * KP;
        const float* Vt = Vs + buf * KTILE * VP;

        // ---- GEMM1: S[32q x 64k] per warp ----
        float sc[2][8][4];
#pragma unroll
        for (int mb = 0; mb < 2; ++mb)
#pragma unroll
            for (int nb = 0; nb < 8; ++nb)
#pragma unroll
                for (int i = 0; i < 4; ++i) sc[mb][nb][i] = 0.0f;

#pragma unroll
        for (int nb = 0; nb < 8; ++nb) {
#pragma unroll
            for (int kb = 0; kb < 4; ++kb) {
                uint32_t bb[2];
                const int key = nb * 8 + g;
                bb[0] = __float_as_uint(Kt[key * KP + kb * 8 + m4]);
                bb[1] = __float_as_uint(Kt[key * KP + kb * 8 + m4 + 4]);
                mma1688(sc[0][nb], qa[0][kb], bb);
                mma1688(sc[1][nb], qa[1][kb], bb);
            }
        }

        // ---- exp2 (base-2 logits), round to tf32, accumulate row sums ----
#pragma unroll
        for (int mb = 0; mb < 2; ++mb)
#pragma unroll
            for (int nb = 0; nb < 8; ++nb) {
                const uint32_t t0 = tf32r(ex2(sc[mb][nb][0]));
                const uint32_t t1 = tf32r(ex2(sc[mb][nb][1]));
                const uint32_t t2 = tf32r(ex2(sc[mb][nb][2]));
                const uint32_t t3 = tf32r(ex2(sc[mb][nb][3]));
                sc[mb][nb][0] = __uint_as_float(t0);
                sc[mb][nb][1] = __uint_as_float(t1);
                sc[mb][nb][2] = __uint_as_float(t2);
                sc[mb][nb][3] = __uint_as_float(t3);
                ls[mb][0] += __uint_as_float(t0) + __uint_as_float(t1);
                ls[mb][1] += __uint_as_float(t2) + __uint_as_float(t3);
            }

        // ---- GEMM2 in two key-halves through warp-private P smem ----
#pragma unroll
        for (int kh = 0; kh < 2; ++kh) {
            __syncwarp();
#pragma unroll
            for (int mb = 0; mb < 2; ++mb)
#pragma unroll
                for (int nb = 0; nb < 4; ++nb) {
                    const int nbb = kh * 4 + nb;
                    *(float2*)&Pw[(mb * 16 + g) * PP + nb * 8 + 2 * m4] =
                        make_float2(sc[mb][nbb][0], sc[mb][nbb][1]);
                    *(float2*)&Pw[(mb * 16 + g + 8) * PP + nb * 8 + 2 * m4] =
                        make_float2(sc[mb][nbb][2], sc[mb][nbb][3]);
                }
            __syncwarp();
#pragma unroll
            for (int kb = 0; kb < 4; ++kb) {
                uint32_t pa[2][4];
#pragma unroll
                for (int mb = 0; mb < 2; ++mb) {
                    pa[mb][0] = __float_as_uint(Pw[(mb * 16 + g) * PP + kb * 8 + m4]);
                    pa[mb][1] = __float_as_uint(Pw[(mb * 16 + g + 8) * PP + kb * 8 + m4]);
                    pa[mb][2] = __float_as_uint(Pw[(mb * 16 + g) * PP + kb * 8 + m4 + 4]);
                    pa[mb][3] = __float_as_uint(Pw[(mb * 16 + g + 8) * PP + kb * 8 + m4 + 4]);
                }
#pragma unroll
                for (int nb = 0; nb < 4; ++nb) {
                    uint32_t bb[2];
                    const int key = kh * 32 + kb * 8;
                    bb[0] = __float_as_uint(Vt[(key + m4) * VP + nb * 8 + g]);
                    bb[1] = __float_as_uint(Vt[(key + m4 + 4) * VP + nb * 8 + g]);
                    mma1688(oc[0][nb], pa[0], bb);
                    mma1688(oc[1][nb], pa[1], bb);
                }
            }
        }
        __syncthreads();   // all warps done with buf before it is refilled
    }

    // ---- epilogue: reduce row sums over the 4 lanes of each row group ----
#pragma unroll
    for (int mb = 0; mb < 2; ++mb)
#pragma unroll
        for (int rh = 0; rh < 2; ++rh) {
            float v = ls[mb][rh];
            v += __shfl_xor_sync(0xffffffffu, v, 1);
            v += __shfl_xor_sync(0xffffffffu, v, 2);
            ls[mb][rh] = 1.0f / v;
        }

    float* Og = g_O + ((size_t)b * CDIM + h * HDIM) * NQ + (size_t)qt * QT;
#pragma unroll
    for (int mb = 0; mb < 2; ++mb)
#pragma unroll
        for (int nb = 0; nb < 4; ++nb) {
            const int rA = w * 32 + mb * 16 + g, rB = rA + 8;
            const int d0 = nb * 8 + 2 * m4;
            Og[(size_t)d0 * NQ + rA]       = oc[mb][nb][0] * ls[mb][0];
            Og[(size_t)(d0 + 1) * NQ + rA] = oc[mb][nb][1] * ls[mb][0];
            Og[(size_t)d0 * NQ + rB]       = oc[mb][nb][2] * ls[mb][1];
            Og[(size_t)(d0 + 1) * NQ + rB] = oc[mb][nb][3] * ls[mb][1];
        }
}

// =====================================================================
extern "C" void kernel_launch(void* const* d_in, const int* in_sizes, int n_in,
                              void* d_out, int out_size)
{
    const float* x  = (const float*)d_in[0];
    const float* Wq = (const float*)d_in[1];
    const float* bq = (const float*)d_in[2];
    const float* Wk = (const float*)d_in[3];
    const float* bk = (const float*)d_in[4];
    const float* Wv = (const float*)d_in[5];
    const float* bv = (const float*)d_in[6];
    const float* Wo = (const float*)d_in[7];
    const float* bo = (const float*)d_in[8];
    float* out = (float*)d_out;
    (void)in_sizes; (void)n_in; (void)out_size;

    float *qp, *kp, *vp, *op;
    cudaGetSymbolAddress((void**)&qp, g_Q);
    cudaGetSymbolAddress((void**)&kp, g_K);
    cudaGetSymbolAddress((void**)&vp, g_V);
    cudaGetSymbolAddress((void**)&op, g_O);

    const int attn_smem = ATTN_SMEM_FLOATS * 4;   // 57344 B
    cudaFuncSetAttribute(attn_mma, cudaFuncAttributeMaxDynamicSharedMemorySize, attn_smem);

    dim3 gp(NQ / 64, BATCH, 1);
    gemm_proj<<<gp, 256>>>(x, Wq, bq, qp, 2);   // Q: head layout, *scale*log2e, tf32
    gemm_proj<<<gp, 256>>>(x, Wk, bk, kp, 1);   // K: head layout, tf32
    gemm_proj<<<gp, 256>>>(x, Wv, bv, vp, 1);   // V: head layout, tf32
    attn_mma<<<dim3(NQ / QT, NHEAD, BATCH), 128, attn_smem>>>();
    gemm_proj<<<gp, 256>>>(op, Wo, bo, out, 0); // final (B,C,H,W)
}

// round 5
// speedup vs baseline: 2.1793x; 2.1793x over previous
#include <cuda_runtime.h>
#include <cstdint>

#define BATCH 8
#define CDIM  128
#define NHEAD 4
#define HDIM  32
#define NQ    4096
#define NKT   64           // key tiles of 64 keys

// Scratch (allocation-free rule: __device__ globals)
__device__ uint16_t g_Qh[(size_t)BATCH * NHEAD * NQ * HDIM];  // [b][h][n][d] fp16, pre-scaled
__device__ uint16_t g_Kh[(size_t)BATCH * NHEAD * NQ * HDIM];  // [b][h][n][d] fp16
__device__ uint16_t g_Vh[(size_t)BATCH * NHEAD * NQ * HDIM];  // [b][h][n][d] fp16
__device__ float    g_O [(size_t)BATCH * CDIM * NQ];          // [b][e][n] f32 channel-major

#define SCALE_LOG2E 0.25506770310758727f   // (1/sqrt(32)) * log2(e)
#define ONE2 0x3C003C00u                   // half2 {1.0, 1.0}

// ---------------- helpers ----------------
__device__ __forceinline__ unsigned long long pk2(float lo, float hi) {
    unsigned long long r;
    asm("mov.b64 %0, {%1, %2};" : "=l"(r) : "f"(lo), "f"(hi));
    return r;
}
__device__ __forceinline__ float2 upk(unsigned long long v) {
    float2 f;
    asm("mov.b64 {%0, %1}, %2;" : "=f"(f.x), "=f"(f.y) : "l"(v));
    return f;
}
__device__ __forceinline__ void fma2(unsigned long long& d, unsigned long long a, unsigned long long b) {
    asm("fma.rn.f32x2 %0, %1, %2, %0;" : "+l"(d) : "l"(a), "l"(b));
}
__device__ __forceinline__ uint32_t h2pack(float lo, float hi) {   // -> half2 {lo, hi}
    uint32_t r;
    asm("cvt.rn.f16x2.f32 %0, %1, %2;" : "=r"(r) : "f"(hi), "f"(lo));
    return r;
}
__device__ __forceinline__ uint32_t ex2h2(uint32_t x) {            // exp2 on both halves
    uint32_t r;
    asm("ex2.approx.f16x2 %0, %1;" : "=r"(r) : "r"(x));
    return r;
}
__device__ __forceinline__ uint32_t smem_u32(const void* p) {
    uint32_t a;
    asm("{ .reg .u64 t; cvta.to.shared.u64 t, %1; cvt.u32.u64 %0, t; }" : "=r"(a) : "l"(p));
    return a;
}
__device__ __forceinline__ void cpa16(uint32_t dst, const void* src) {
    asm volatile("cp.async.cg.shared.global [%0], [%1], 16;" :: "r"(dst), "l"(src));
}
#define CP_COMMIT() asm volatile("cp.async.commit_group;" ::: "memory")
#define CP_WAIT(n)  asm volatile("cp.async.wait_group %0;" :: "n"(n) : "memory")

// fp16 m16n8k16 MMA, f32 accumulate (sm_80+, arch-agnostic)
__device__ __forceinline__ void mma16816(float* c, const uint32_t* a, uint32_t b0, uint32_t b1) {
    asm volatile("mma.sync.aligned.m16n8k16.row.col.f32.f16.f16.f32 "
        "{%0,%1,%2,%3}, {%4,%5,%6,%7}, {%8,%9}, {%0,%1,%2,%3};"
        : "+f"(c[0]), "+f"(c[1]), "+f"(c[2]), "+f"(c[3])
        : "r"(a[0]), "r"(a[1]), "r"(a[2]), "r"(a[3]), "r"(b0), "r"(b1));
}
__device__ __forceinline__ void ldsm4(uint32_t* r, uint32_t addr) {
    asm volatile("ldmatrix.sync.aligned.m8n8.x4.shared.b16 {%0,%1,%2,%3}, [%4];"
        : "=r"(r[0]), "=r"(r[1]), "=r"(r[2]), "=r"(r[3]) : "r"(addr));
}
__device__ __forceinline__ void ldsm4t(uint32_t* r, uint32_t addr) {
    asm volatile("ldmatrix.sync.aligned.m8n8.x4.trans.shared.b16 {%0,%1,%2,%3}, [%4];"
        : "=r"(r[0]), "=r"(r[1]), "=r"(r[2]), "=r"(r[3]) : "r"(addr));
}

// =====================================================================
// Projection GEMM.  acc[e][n] = sum_c W[e][c]*X[b][c][n] + bias[e]
// fused=1: z=0 -> Q (fp16 [b][h][n][d], *scale*log2e)
//          z=1 -> K (fp16 [b][h][n][d])
//          z=2 -> V (fp16 [b][h][n][d])
// fused=0: W0/B0 -> OutF [b][e][n] f32 (final output)
// =====================================================================
__global__ __launch_bounds__(256)
void gemm_proj(const float* __restrict__ X,
               const float* __restrict__ W0, const float* __restrict__ B0,
               const float* __restrict__ W1, const float* __restrict__ B1,
               const float* __restrict__ W2, const float* __restrict__ B2,
               float* __restrict__ OutF, int fused)
{
    __shared__ __align__(16) float Ws[32][132];
    __shared__ __align__(16) float Xs[32][68];

    int mode;                       // 2=Q, 1=K, 3=V, 0=final
    const float *Wt, *bias;
    if (fused) {
        const int z = blockIdx.z;
        mode = (z == 0) ? 2 : ((z == 1) ? 1 : 3);
        Wt   = (z == 0) ? W0 : ((z == 1) ? W1 : W2);
        bias = (z == 0) ? B0 : ((z == 1) ? B1 : B2);
    } else { mode = 0; Wt = W0; bias = B0; }

    const int b   = blockIdx.y;
    const int n0  = blockIdx.x * 64;
    const int tid = threadIdx.x;
    const int e0  = (tid >> 4) * 8;
    const int nn0 = (tid & 15) * 4;
    const float* Xb = X + (size_t)b * CDIM * NQ;

    unsigned long long acc2[4][4];
#pragma unroll
    for (int i = 0; i < 4; ++i)
#pragma unroll
        for (int j = 0; j < 4; ++j) acc2[i][j] = 0ULL;

    for (int kt = 0; kt < 4; ++kt) {
        const int k0 = kt * 32;
        {
            const int cc = (tid & 7) * 4;
#pragma unroll
            for (int pass = 0; pass < 4; ++pass) {
                const int e = (tid >> 3) + pass * 32;
                const float4 w4 = *(const float4*)&Wt[e * CDIM + k0 + cc];
                Ws[cc + 0][e] = w4.x; Ws[cc + 1][e] = w4.y;
                Ws[cc + 2][e] = w4.z; Ws[cc + 3][e] = w4.w;
            }
        }
        {
            const int nn = (tid & 15) * 4;
#pragma unroll
            for (int pass = 0; pass < 2; ++pass) {
                const int kk = (tid >> 4) + pass * 16;
                *(float4*)&Xs[kk][nn] =
                    *(const float4*)&Xb[(size_t)(k0 + kk) * NQ + n0 + nn];
            }
        }
        __syncthreads();

#pragma unroll 8
        for (int kk = 0; kk < 32; ++kk) {
            const ulonglong2 wA = *(const ulonglong2*)&Ws[kk][e0];
            const ulonglong2 wB = *(const ulonglong2*)&Ws[kk][e0 + 4];
            const float4 xv = *(const float4*)&Xs[kk][nn0];
            unsigned long long xb;
            xb = pk2(xv.x, xv.x);
            fma2(acc2[0][0], wA.x, xb); fma2(acc2[1][0], wA.y, xb);
            fma2(acc2[2][0], wB.x, xb); fma2(acc2[3][0], wB.y, xb);
            xb = pk2(xv.y, xv.y);
            fma2(acc2[0][1], wA.x, xb); fma2(acc2[1][1], wA.y, xb);
            fma2(acc2[2][1], wB.x, xb); fma2(acc2[3][1], wB.y, xb);
            xb = pk2(xv.z, xv.z);
            fma2(acc2[0][2], wA.x, xb); fma2(acc2[1][2], wA.y, xb);
            fma2(acc2[2][2], wB.x, xb); fma2(acc2[3][2], wB.y, xb);
            xb = pk2(xv.w, xv.w);
            fma2(acc2[0][3], wA.x, xb); fma2(acc2[1][3], wA.y, xb);
            fma2(acc2[2][3], wB.x, xb); fma2(acc2[3][3], wB.y, xb);
        }
        __syncthreads();
    }

    const float4 bl = *(const float4*)&bias[e0];
    const float4 bh = *(const float4*)&bias[e0 + 4];
    const float bv8[8] = {bl.x, bl.y, bl.z, bl.w, bh.x, bh.y, bh.z, bh.w};

    if (mode == 0) {
#pragma unroll
        for (int i = 0; i < 8; ++i) {
            float vals[4];
#pragma unroll
            for (int j = 0; j < 4; ++j) {
                const float2 pp = upk(acc2[i >> 1][j]);
                vals[j] = ((i & 1) ? pp.y : pp.x) + bv8[i];
            }
            *(float4*)&OutF[((size_t)b * CDIM + e0 + i) * NQ + n0 + nn0] =
                make_float4(vals[0], vals[1], vals[2], vals[3]);
        }
        return;
    }

    const float mul = (mode == 2) ? SCALE_LOG2E : 1.0f;
    uint16_t* dsth = (mode == 2) ? g_Qh : ((mode == 1) ? g_Kh : g_Vh);
    const int h  = e0 >> 5;
    const int d0 = e0 & 31;
    uint16_t* dst = dsth + ((size_t)(b * NHEAD + h) * NQ) * HDIM + d0;
#pragma unroll
    for (int j = 0; j < 4; ++j) {
        const int n = n0 + nn0 + j;
        float v[8];
#pragma unroll
        for (int i = 0; i < 8; ++i) {
            const float2 pp = upk(acc2[i >> 1][j]);
            v[i] = (((i & 1) ? pp.y : pp.x) + bv8[i]) * mul;
        }
        uint4 st;
        st.x = h2pack(v[0], v[1]); st.y = h2pack(v[2], v[3]);
        st.z = h2pack(v[4], v[5]); st.w = h2pack(v[6], v[7]);
        *(uint4*)&dst[(size_t)n * HDIM] = st;
    }
}

// =====================================================================
// Flash attention, fp16 m16n8k16, FA2 register pipeline.
// CTA = 128 q-rows of one (b,h), 4 warps; warp owns 32 q-rows.
// P stays in registers (S C-frag == next A-frag). Row sums via an
// extra MMA against a constant all-ones B fragment. Max-free base-2
// softmax via ex2.approx.f16x2. K/V double-buffered cp.async with
// XOR-swizzled 64B rows; fragments via ldmatrix.x4 (K) / .x4.trans (V).
// =====================================================================
__global__ __launch_bounds__(128, 3)
void attn_fa()
{
    __shared__ __align__(16) uint4 Ksm[2][64][4];   // [buf][key][chunk]  8 KB
    __shared__ __align__(16) uint4 Vsm[2][64][4];   // [buf][key][chunk]  8 KB

    const int qt = blockIdx.x, h = blockIdx.y, b = blockIdx.z;
    const int tid = threadIdx.x;
    const int w = tid >> 5, lane = tid & 31;
    const int g = lane >> 2, m4 = lane & 3;

    const uint16_t* Qh = g_Qh + ((size_t)(b * NHEAD + h) * NQ + (size_t)qt * 128 + w * 32) * HDIM;
    const uint4* Kg4 = (const uint4*)(g_Kh + (size_t)(b * NHEAD + h) * NQ * HDIM);
    const uint4* Vg4 = (const uint4*)(g_Vh + (size_t)(b * NHEAD + h) * NQ * HDIM);

    // ---- Q A-fragments (fp16), loaded once, live all kernel ----
    uint32_t qa[2][2][4];
#pragma unroll
    for (int mb = 0; mb < 2; ++mb)
#pragma unroll
        for (int kb = 0; kb < 2; ++kb) {
            const int r0 = mb * 16 + g;
            qa[mb][kb][0] = *(const uint32_t*)&Qh[(size_t)r0 * HDIM + kb * 16 + 2 * m4];
            qa[mb][kb][1] = *(const uint32_t*)&Qh[(size_t)(r0 + 8) * HDIM + kb * 16 + 2 * m4];
            qa[mb][kb][2] = *(const uint32_t*)&Qh[(size_t)r0 * HDIM + kb * 16 + 8 + 2 * m4];
            qa[mb][kb][3] = *(const uint32_t*)&Qh[(size_t)(r0 + 8) * HDIM + kb * 16 + 8 + 2 * m4];
        }

    // oc[mb][0..3] = O d-tiles; oc[mb][4] = row sums (ones-MMA)
    float oc[2][5][4];
#pragma unroll
    for (int mb = 0; mb < 2; ++mb)
#pragma unroll
        for (int nb = 0; nb < 5; ++nb)
#pragma unroll
            for (int i = 0; i < 4; ++i) oc[mb][nb][i] = 0.0f;

    // ---- per-thread ldmatrix base addresses ----
    const int lt = lane >> 3;            // tile index 0..3
    const int lr = lane & 7;             // row within tile
    const int ls = (lr >> 1) & 3;        // XOR swizzle term
    // K tile t covers d-chunk t of key rows nb*8+lr
    const uint32_t ksm0 = smem_u32(&Ksm[0][lr][lt ^ ls]);
    // V tile t covers key-octet t (rows lt*8+lr), chunk nbo^ls added at use
    const uint32_t vsm0 = smem_u32(&Vsm[0][lt * 8 + lr][0]);

    // ---- per-thread cp.async slots (key = c>>2, ch = c&3; gchunk == c) ----
    const int c0 = tid, c1 = tid + 128;
    const int k0i = c0 >> 2, h0 = c0 & 3, k1i = c1 >> 2, h1 = c1 & 3;
    const uint32_t sk0 = smem_u32(&Ksm[0][k0i][h0 ^ ((k0i >> 1) & 3)]);
    const uint32_t sk1 = smem_u32(&Ksm[0][k1i][h1 ^ ((k1i >> 1) & 3)]);
    const uint32_t sv0 = smem_u32(&Vsm[0][k0i][h0 ^ ((k0i >> 1) & 3)]);
    const uint32_t sv1 = smem_u32(&Vsm[0][k1i][h1 ^ ((k1i >> 1) & 3)]);

    auto load_tile = [&](int kt, int buf) {
        const uint32_t so = (uint32_t)buf * 4096u;
        const size_t go = (size_t)kt * 256;
        cpa16(sk0 + so, Kg4 + go + c0);
        cpa16(sk1 + so, Kg4 + go + c1);
        cpa16(sv0 + so, Vg4 + go + c0);
        cpa16(sv1 + so, Vg4 + go + c1);
    };

    load_tile(0, 0); CP_COMMIT();

    for (int kt = 0; kt < NKT; ++kt) {
        const int buf = kt & 1;
        if (kt + 1 < NKT) { load_tile(kt + 1, buf ^ 1); CP_COMMIT(); CP_WAIT(1); }
        else              { CP_WAIT(0); }
        __syncthreads();     // all warps' cp.async for buf visible

        const uint32_t kbase = ksm0 + (uint32_t)buf * 4096u;
        const uint32_t vbase = vsm0 + (uint32_t)buf * 4096u;

#pragma unroll
        for (int kh = 0; kh < 2; ++kh) {
            // ---- GEMM1: S[32q x 32k] for keys [kh*32, kh*32+32) ----
            float sc[2][4][4];
#pragma unroll
            for (int mb = 0; mb < 2; ++mb)
#pragma unroll
                for (int nbi = 0; nbi < 4; ++nbi)
#pragma unroll
                    for (int i = 0; i < 4; ++i) sc[mb][nbi][i] = 0.0f;

#pragma unroll
            for (int nbi = 0; nbi < 4; ++nbi) {
                uint32_t kr[4];
                ldsm4(kr, kbase + (uint32_t)(kh * 4 + nbi) * 512u);
                mma16816(sc[0][nbi], qa[0][0], kr[0], kr[1]);
                mma16816(sc[0][nbi], qa[0][1], kr[2], kr[3]);
                mma16816(sc[1][nbi], qa[1][0], kr[0], kr[1]);
                mma16816(sc[1][nbi], qa[1][1], kr[2], kr[3]);
            }

            // ---- softmax: cvt f32->f16x2, exp2 both halves, pack A-frags ----
            uint32_t pa[2][2][4];   // [mb][kstep(16 keys)][a0..a3]
#pragma unroll
            for (int mb = 0; mb < 2; ++mb)
#pragma unroll
                for (int nbi = 0; nbi < 4; ++nbi) {
                    const int ks = nbi >> 1, hi2 = (nbi & 1) * 2;
                    pa[mb][ks][hi2]     = ex2h2(h2pack(sc[mb][nbi][0], sc[mb][nbi][1]));
                    pa[mb][ks][hi2 + 1] = ex2h2(h2pack(sc[mb][nbi][2], sc[mb][nbi][3]));
                }

            // ---- GEMM2: O += P @ V over these 32 keys ----
#pragma unroll
            for (int nbo = 0; nbo < 4; ++nbo) {
                uint32_t vr[4];
                ldsm4t(vr, vbase + (uint32_t)(kh * 2048) + ((uint32_t)(nbo ^ ls) << 4));
                mma16816(oc[0][nbo], pa[0][0], vr[0], vr[1]);
                mma16816(oc[0][nbo], pa[0][1], vr[2], vr[3]);
                mma16816(oc[1][nbo], pa[1][0], vr[0], vr[1]);
                mma16816(oc[1][nbo], pa[1][1], vr[2], vr[3]);
            }
            // ---- row sums: P @ ones ----
            mma16816(oc[0][4], pa[0][0], ONE2, ONE2);
            mma16816(oc[0][4], pa[0][1], ONE2, ONE2);
            mma16816(oc[1][4], pa[1][0], ONE2, ONE2);
            mma16816(oc[1][4], pa[1][1], ONE2, ONE2);
        }
        __syncthreads();     // all warps done reading buf before refill
    }

    // ---- epilogue: normalize, write channel-major g_O[b][e][n] ----
    float* base = g_O + ((size_t)b * CDIM + h * HDIM) * NQ;
#pragma unroll
    for (int mb = 0; mb < 2; ++mb) {
        const float inv0 = 1.0f / oc[mb][4][0];   // row g
        const float inv1 = 1.0f / oc[mb][4][2];   // row g+8
        const int rA = qt * 128 + w * 32 + mb * 16 + g;
#pragma unroll
        for (int nbo = 0; nbo < 4; ++nbo) {
            const int d0 = nbo * 8 + 2 * m4;
            base[(size_t)d0 * NQ + rA]           = oc[mb][nbo][0] * inv0;
            base[(size_t)(d0 + 1) * NQ + rA]     = oc[mb][nbo][1] * inv0;
            base[(size_t)d0 * NQ + rA + 8]       = oc[mb][nbo][2] * inv1;
            base[(size_t)(d0 + 1) * NQ + rA + 8] = oc[mb][nbo][3] * inv1;
        }
    }
}

// =====================================================================
extern "C" void kernel_launch(void* const* d_in, const int* in_sizes, int n_in,
                              void* d_out, int out_size)
{
    const float* x  = (const float*)d_in[0];
    const float* Wq = (const float*)d_in[1];
    const float* bq = (const float*)d_in[2];
    const float* Wk = (const float*)d_in[3];
    const float* bk = (const float*)d_in[4];
    const float* Wv = (const float*)d_in[5];
    const float* bv = (const float*)d_in[6];
    const float* Wo = (const float*)d_in[7];
    const float* bo = (const float*)d_in[8];
    float* out = (float*)d_out;
    (void)in_sizes; (void)n_in; (void)out_size;

    float* op;
    cudaGetSymbolAddress((void**)&op, g_O);

    gemm_proj<<<dim3(NQ / 64, BATCH, 3), 256>>>(x, Wq, bq, Wk, bk, Wv, bv, nullptr, 1);
    attn_fa<<<dim3(NQ / 128, NHEAD, BATCH), 128>>>();
    gemm_proj<<<dim3(NQ / 64, BATCH, 1), 256>>>(op, Wo, bo, nullptr, nullptr, nullptr, nullptr, out, 0);
}

// round 6
// speedup vs baseline: 2.9344x; 1.3465x over previous
#include <cuda_runtime.h>
#include <cstdint>

#define BATCH 8
#define CDIM  128
#define NHEAD 4
#define HDIM  32
#define NQ    4096
#define NKT   64           // key tiles of 64 keys

// Scratch (allocation-free rule: __device__ globals)
__device__ uint16_t g_Xh[(size_t)BATCH * NQ * CDIM];          // [b][n][c] fp16 (x tokens)
__device__ uint16_t g_Wh[4 * CDIM * CDIM];                    // [z][e][c] fp16 (Wq,Wk,Wv,Wo)
__device__ uint16_t g_Qh[(size_t)BATCH * NHEAD * NQ * HDIM];  // [b][h][n][d] fp16, pre-scaled
__device__ uint16_t g_Kh[(size_t)BATCH * NHEAD * NQ * HDIM];  // [b][h][n][d] fp16
__device__ uint16_t g_Vh[(size_t)BATCH * NHEAD * NQ * HDIM];  // [b][h][n][d] fp16
__device__ uint16_t g_Oh[(size_t)BATCH * NQ * CDIM];          // [b][n][e] fp16 (attn out)

#define SCALE_LOG2E 0.25506770310758727f   // (1/sqrt(32)) * log2(e)
#define ONE2 0x3C003C00u                   // half2 {1.0, 1.0}

// ---------------- helpers ----------------
__device__ __forceinline__ uint32_t h2pack(float lo, float hi) {   // -> half2 {lo, hi}
    uint32_t r;
    asm("cvt.rn.f16x2.f32 %0, %1, %2;" : "=r"(r) : "f"(hi), "f"(lo));
    return r;
}
__device__ __forceinline__ uint32_t ex2h2(uint32_t x) {            // exp2 on both halves
    uint32_t r;
    asm("ex2.approx.f16x2 %0, %1;" : "=r"(r) : "r"(x));
    return r;
}
__device__ __forceinline__ uint32_t smem_u32(const void* p) {
    uint32_t a;
    asm("{ .reg .u64 t; cvta.to.shared.u64 t, %1; cvt.u32.u64 %0, t; }" : "=r"(a) : "l"(p));
    return a;
}
__device__ __forceinline__ void cpa16(uint32_t dst, const void* src) {
    asm volatile("cp.async.cg.shared.global [%0], [%1], 16;" :: "r"(dst), "l"(src));
}
#define CP_COMMIT() asm volatile("cp.async.commit_group;" ::: "memory")
#define CP_WAIT(n)  asm volatile("cp.async.wait_group %0;" :: "n"(n) : "memory")

// fp16 m16n8k16 MMA, f32 accumulate (sm_80+, arch-agnostic)
__device__ __forceinline__ void mma16816(float* c, const uint32_t* a, uint32_t b0, uint32_t b1) {
    asm volatile("mma.sync.aligned.m16n8k16.row.col.f32.f16.f16.f32 "
        "{%0,%1,%2,%3}, {%4,%5,%6,%7}, {%8,%9}, {%0,%1,%2,%3};"
        : "+f"(c[0]), "+f"(c[1]), "+f"(c[2]), "+f"(c[3])
        : "r"(a[0]), "r"(a[1]), "r"(a[2]), "r"(a[3]), "r"(b0), "r"(b1));
}
__device__ __forceinline__ void ldsm4(uint32_t* r, uint32_t addr) {
    asm volatile("ldmatrix.sync.aligned.m8n8.x4.shared.b16 {%0,%1,%2,%3}, [%4];"
        : "=r"(r[0]), "=r"(r[1]), "=r"(r[2]), "=r"(r[3]) : "r"(addr));
}
__device__ __forceinline__ void ldsm4t(uint32_t* r, uint32_t addr) {
    asm volatile("ldmatrix.sync.aligned.m8n8.x4.trans.shared.b16 {%0,%1,%2,%3}, [%4];"
        : "=r"(r[0]), "=r"(r[1]), "=r"(r[2]), "=r"(r[3]) : "r"(addr));
}

// =====================================================================
// conv_x: x[b][c][n] f32 -> g_Xh[b][n][c] fp16 (transpose via smem)
// =====================================================================
__global__ __launch_bounds__(256)
void conv_x(const float* __restrict__ x)
{
    __shared__ float sm[32][65];
    const int n0 = blockIdx.x * 64, c0 = blockIdx.y * 32, b = blockIdx.z;
    const int tid = threadIdx.x;
    const float* src = x + ((size_t)b * CDIM + c0) * NQ + n0;
#pragma unroll
    for (int i = 0; i < 8; ++i) {
        const int lin = tid + i * 256;          // 32 rows x 64 cols
        const int r = lin >> 6, nn = lin & 63;
        sm[r][nn] = src[(size_t)r * NQ + nn];
    }
    __syncthreads();
    uint16_t* dst = g_Xh + ((size_t)b * NQ + n0) * CDIM + c0;
#pragma unroll
    for (int i = 0; i < 4; ++i) {
        const int lin = tid + i * 256;          // 64 n x 16 c-pairs
        const int n = lin >> 4, cp = lin & 15;
        *(uint32_t*)&dst[(size_t)n * CDIM + 2 * cp] = h2pack(sm[2 * cp][n], sm[2 * cp + 1][n]);
    }
}

// =====================================================================
// conv_w: 4x (128x128 f32) -> g_Wh fp16, same [e][c] layout
// =====================================================================
__global__ __launch_bounds__(256)
void conv_w(const float* __restrict__ Wq, const float* __restrict__ Wk,
            const float* __restrict__ Wv, const float* __restrict__ Wo)
{
    const int lin = (blockIdx.x * 256 + threadIdx.x) * 2;   // grid 32 -> 16384 elems/matrix
    const float* src[4] = {Wq, Wk, Wv, Wo};
#pragma unroll
    for (int z = 0; z < 4; ++z)
        *(uint32_t*)&g_Wh[z * CDIM * CDIM + lin] = h2pack(src[z][lin], src[z][lin + 1]);
}

// =====================================================================
// proj_qkv: C[tok][e] = Xh[tok][:] @ W_z[e][:]^T + bias_z, fp16 mma.
// CTA: 128 tokens x 128 e, 8 warps (warp = 16 tokens x 128 e).
// z: 0=Q (scaled), 1=K, 2=V; output [b][h][n][d] fp16.
// smem: X tile 32KB + W 32KB, XOR-swizzled 16B chunks (256B rows).
// =====================================================================
__global__ __launch_bounds__(256, 2)
void proj_qkv(const float* __restrict__ bq, const float* __restrict__ bk,
              const float* __restrict__ bv)
{
    extern __shared__ uint4 smem4[];
    uint4* Xs = smem4;            // [128 tok][16 ch]
    uint4* Ws = smem4 + 2048;     // [128 e][16 ch]

    const int qt = blockIdx.x, b = blockIdx.y, z = blockIdx.z;
    const int tid = threadIdx.x, w = tid >> 5, lane = tid & 31;
    const int g = lane >> 2, m4 = lane & 3, lr = lane & 7;

    const uint4* Xg = (const uint4*)g_Xh + ((size_t)b * NQ + qt * 128) * 16;
    const uint4* Wg = (const uint4*)g_Wh + z * 2048;
    const float* bias = (z == 0) ? bq : ((z == 1) ? bk : bv);
    const float mul = (z == 0) ? SCALE_LOG2E : 1.0f;
    uint16_t* dst = (z == 0) ? g_Qh : ((z == 1) ? g_Kh : g_Vh);

#pragma unroll
    for (int i = 0; i < 8; ++i) {
        const int c = tid + i * 256;
        const int r = c >> 4, ch = c & 15;
        cpa16(smem_u32(&Xs[r * 16 + (ch ^ (r & 7))]), Xg + c);
    }
#pragma unroll
    for (int i = 0; i < 8; ++i) {
        const int c = tid + i * 256;
        const int r = c >> 4, ch = c & 15;
        cpa16(smem_u32(&Ws[r * 16 + (ch ^ (r & 7))]), Wg + c);
    }
    CP_COMMIT(); CP_WAIT(0);
    __syncthreads();

    float acc[16][4];
#pragma unroll
    for (int nb = 0; nb < 16; ++nb)
#pragma unroll
        for (int i = 0; i < 4; ++i) acc[nb][i] = 0.0f;

    // A-frag ldmatrix addressing (rows = tokens, non-trans)
    const uint32_t Xbase = smem_u32(Xs) + (uint32_t)(w * 16 + lr + ((lane >> 3) & 1) * 8) * 256u;
    const int achsel = (lane >> 4) & 1;
    // B-frag ldmatrix addressing (rows = e, 4 chunk groups)
    const uint32_t Wbase = smem_u32(Ws);
    const int bg = lane >> 3;

#pragma unroll
    for (int kbb = 0; kbb < 4; ++kbb) {
        uint32_t a0[4], a1[4];
        ldsm4(a0, Xbase + (uint32_t)(((4 * kbb + achsel) ^ lr) << 4));
        ldsm4(a1, Xbase + (uint32_t)(((4 * kbb + 2 + achsel) ^ lr) << 4));
#pragma unroll
        for (int nb = 0; nb < 16; ++nb) {
            uint32_t br[4];
            ldsm4(br, Wbase + (uint32_t)(nb * 8 + lr) * 256u
                      + (uint32_t)(((kbb * 4 + bg) ^ lr) << 4));
            mma16816(acc[nb], a0, br[0], br[1]);
            mma16816(acc[nb], a1, br[2], br[3]);
        }
    }

    const int tokA = qt * 128 + w * 16 + g;
#pragma unroll
    for (int nb = 0; nb < 16; ++nb) {
        const int e = nb * 8 + 2 * m4;
        const float b0 = bias[e], b1 = bias[e + 1];
        const int h = e >> 5, d = e & 31;
        uint16_t* p = dst + ((size_t)(b * NHEAD + h) * NQ + tokA) * HDIM + d;
        *(uint32_t*)p              = h2pack((acc[nb][0] + b0) * mul, (acc[nb][1] + b1) * mul);
        *(uint32_t*)(p + 8 * HDIM) = h2pack((acc[nb][2] + b0) * mul, (acc[nb][3] + b1) * mul);
    }
}

// =====================================================================
// proj_out: C[tok][e] = Oh[tok][:] @ Wo[e][:]^T + bo, then smem
// transpose -> coalesced f32 stores to out[b][e][n] (== B,C,H,W).
// =====================================================================
__global__ __launch_bounds__(256, 1)
void proj_out(const float* __restrict__ bo, float* __restrict__ out)
{
    extern __shared__ uint4 smem4[];
    uint4* Os = smem4;            // [128 tok][16 ch]
    uint4* Ws = smem4 + 2048;     // [128 e][16 ch]
    float* stg = (float*)(smem4 + 4096);   // [64 e][132 tok]

    const int qt = blockIdx.x, b = blockIdx.y;
    const int tid = threadIdx.x, w = tid >> 5, lane = tid & 31;
    const int g = lane >> 2, m4 = lane & 3, lr = lane & 7;

    const uint4* Og = (const uint4*)g_Oh + ((size_t)b * NQ + qt * 128) * 16;
    const uint4* Wg = (const uint4*)g_Wh + 3 * 2048;

#pragma unroll
    for (int i = 0; i < 8; ++i) {
        const int c = tid + i * 256;
        const int r = c >> 4, ch = c & 15;
        cpa16(smem_u32(&Os[r * 16 + (ch ^ (r & 7))]), Og + c);
    }
#pragma unroll
    for (int i = 0; i < 8; ++i) {
        const int c = tid + i * 256;
        const int r = c >> 4, ch = c & 15;
        cpa16(smem_u32(&Ws[r * 16 + (ch ^ (r & 7))]), Wg + c);
    }
    CP_COMMIT(); CP_WAIT(0);
    __syncthreads();

    float acc[16][4];
#pragma unroll
    for (int nb = 0; nb < 16; ++nb)
#pragma unroll
        for (int i = 0; i < 4; ++i) acc[nb][i] = 0.0f;

    const uint32_t Obase = smem_u32(Os) + (uint32_t)(w * 16 + lr + ((lane >> 3) & 1) * 8) * 256u;
    const int achsel = (lane >> 4) & 1;
    const uint32_t Wbase = smem_u32(Ws);
    const int bg = lane >> 3;

#pragma unroll
    for (int kbb = 0; kbb < 4; ++kbb) {
        uint32_t a0[4], a1[4];
        ldsm4(a0, Obase + (uint32_t)(((4 * kbb + achsel) ^ lr) << 4));
        ldsm4(a1, Obase + (uint32_t)(((4 * kbb + 2 + achsel) ^ lr) << 4));
#pragma unroll
        for (int nb = 0; nb < 16; ++nb) {
            uint32_t br[4];
            ldsm4(br, Wbase + (uint32_t)(nb * 8 + lr) * 256u
                      + (uint32_t)(((kbb * 4 + bg) ^ lr) << 4));
            mma16816(acc[nb], a0, br[0], br[1]);
            mma16816(acc[nb], a1, br[2], br[3]);
        }
    }

    // two-phase smem transpose epilogue (e halves of 64)
    const int e_l = tid >> 2, qq = tid & 3;
#pragma unroll
    for (int hh = 0; hh < 2; ++hh) {
        __syncthreads();
#pragma unroll
        for (int nb8 = 0; nb8 < 8; ++nb8) {
            const int nb = hh * 8 + nb8;
            const int el = nb8 * 8 + 2 * m4;
            const int tk = w * 16 + g;
            stg[el * 132 + tk]           = acc[nb][0];
            stg[(el + 1) * 132 + tk]     = acc[nb][1];
            stg[el * 132 + tk + 8]       = acc[nb][2];
            stg[(el + 1) * 132 + tk + 8] = acc[nb][3];
        }
        __syncthreads();
        const int e = hh * 64 + e_l;
        const float bb = bo[e];
        float* orow = out + ((size_t)b * CDIM + e) * NQ + qt * 128 + qq * 4;
#pragma unroll
        for (int i = 0; i < 8; ++i) {
            float4 v = *(const float4*)&stg[e_l * 132 + qq * 4 + i * 16];
            v.x += bb; v.y += bb; v.z += bb; v.w += bb;
            *(float4*)&orow[i * 16] = v;
        }
    }
}

// =====================================================================
// Flash attention, fp16 m16n8k16, FA2 register pipeline (R5, verified).
// Epilogue now writes fp16 token-major g_Oh[b][n][e].
// =====================================================================
__global__ __launch_bounds__(128, 3)
void attn_fa()
{
    __shared__ __align__(16) uint4 Ksm[2][64][4];   // [buf][key][chunk]  8 KB
    __shared__ __align__(16) uint4 Vsm[2][64][4];   // [buf][key][chunk]  8 KB

    const int qt = blockIdx.x, h = blockIdx.y, b = blockIdx.z;
    const int tid = threadIdx.x;
    const int w = tid >> 5, lane = tid & 31;
    const int g = lane >> 2, m4 = lane & 3;

    const uint16_t* Qh = g_Qh + ((size_t)(b * NHEAD + h) * NQ + (size_t)qt * 128 + w * 32) * HDIM;
    const uint4* Kg4 = (const uint4*)(g_Kh + (size_t)(b * NHEAD + h) * NQ * HDIM);
    const uint4* Vg4 = (const uint4*)(g_Vh + (size_t)(b * NHEAD + h) * NQ * HDIM);

    uint32_t qa[2][2][4];
#pragma unroll
    for (int mb = 0; mb < 2; ++mb)
#pragma unroll
        for (int kb = 0; kb < 2; ++kb) {
            const int r0 = mb * 16 + g;
            qa[mb][kb][0] = *(const uint32_t*)&Qh[(size_t)r0 * HDIM + kb * 16 + 2 * m4];
            qa[mb][kb][1] = *(const uint32_t*)&Qh[(size_t)(r0 + 8) * HDIM + kb * 16 + 2 * m4];
            qa[mb][kb][2] = *(const uint32_t*)&Qh[(size_t)r0 * HDIM + kb * 16 + 8 + 2 * m4];
            qa[mb][kb][3] = *(const uint32_t*)&Qh[(size_t)(r0 + 8) * HDIM + kb * 16 + 8 + 2 * m4];
        }

    float oc[2][5][4];
#pragma unroll
    for (int mb = 0; mb < 2; ++mb)
#pragma unroll
        for (int nb = 0; nb < 5; ++nb)
#pragma unroll
            for (int i = 0; i < 4; ++i) oc[mb][nb][i] = 0.0f;

    const int lt = lane >> 3;
    const int lr = lane & 7;
    const int ls = (lr >> 1) & 3;
    const uint32_t ksm0 = smem_u32(&Ksm[0][lr][lt ^ ls]);
    const uint32_t vsm0 = smem_u32(&Vsm[0][lt * 8 + lr][0]);

    const int c0 = tid, c1 = tid + 128;
    const int k0i = c0 >> 2, h0 = c0 & 3, k1i = c1 >> 2, h1 = c1 & 3;
    const uint32_t sk0 = smem_u32(&Ksm[0][k0i][h0 ^ ((k0i >> 1) & 3)]);
    const uint32_t sk1 = smem_u32(&Ksm[0][k1i][h1 ^ ((k1i >> 1) & 3)]);
    const uint32_t sv0 = smem_u32(&Vsm[0][k0i][h0 ^ ((k0i >> 1) & 3)]);
    const uint32_t sv1 = smem_u32(&Vsm[0][k1i][h1 ^ ((k1i >> 1) & 3)]);

    auto load_tile = [&](int kt, int buf) {
        const uint32_t so = (uint32_t)buf * 4096u;
        const size_t go = (size_t)kt * 256;
        cpa16(sk0 + so, Kg4 + go + c0);
        cpa16(sk1 + so, Kg4 + go + c1);
        cpa16(sv0 + so, Vg4 + go + c0);
        cpa16(sv1 + so, Vg4 + go + c1);
    };

    load_tile(0, 0); CP_COMMIT();

    for (int kt = 0; kt < NKT; ++kt) {
        const int buf = kt & 1;
        if (kt + 1 < NKT) { load_tile(kt + 1, buf ^ 1); CP_COMMIT(); CP_WAIT(1); }
        else              { CP_WAIT(0); }
        __syncthreads();

        const uint32_t kbase = ksm0 + (uint32_t)buf * 4096u;
        const uint32_t vbase = vsm0 + (uint32_t)buf * 4096u;

#pragma unroll
        for (int kh = 0; kh < 2; ++kh) {
            float sc[2][4][4];
#pragma unroll
            for (int mb = 0; mb < 2; ++mb)
#pragma unroll
                for (int nbi = 0; nbi < 4; ++nbi)
#pragma unroll
                    for (int i = 0; i < 4; ++i) sc[mb][nbi][i] = 0.0f;

#pragma unroll
            for (int nbi = 0; nbi < 4; ++nbi) {
                uint32_t kr[4];
                ldsm4(kr, kbase + (uint32_t)(kh * 4 + nbi) * 512u);
                mma16816(sc[0][nbi], qa[0][0], kr[0], kr[1]);
                mma16816(sc[0][nbi], qa[0][1], kr[2], kr[3]);
                mma16816(sc[1][nbi], qa[1][0], kr[0], kr[1]);
                mma16816(sc[1][nbi], qa[1][1], kr[2], kr[3]);
            }

            uint32_t pa[2][2][4];
#pragma unroll
            for (int mb = 0; mb < 2; ++mb)
#pragma unroll
                for (int nbi = 0; nbi < 4; ++nbi) {
                    const int ks = nbi >> 1, hi2 = (nbi & 1) * 2;
                    pa[mb][ks][hi2]     = ex2h2(h2pack(sc[mb][nbi][0], sc[mb][nbi][1]));
                    pa[mb][ks][hi2 + 1] = ex2h2(h2pack(sc[mb][nbi][2], sc[mb][nbi][3]));
                }

#pragma unroll
            for (int nbo = 0; nbo < 4; ++nbo) {
                uint32_t vr[4];
                ldsm4t(vr, vbase + (uint32_t)(kh * 2048) + ((uint32_t)(nbo ^ ls) << 4));
                mma16816(oc[0][nbo], pa[0][0], vr[0], vr[1]);
                mma16816(oc[0][nbo], pa[0][1], vr[2], vr[3]);
                mma16816(oc[1][nbo], pa[1][0], vr[0], vr[1]);
                mma16816(oc[1][nbo], pa[1][1], vr[2], vr[3]);
            }
            mma16816(oc[0][4], pa[0][0], ONE2, ONE2);
            mma16816(oc[0][4], pa[0][1], ONE2, ONE2);
            mma16816(oc[1][4], pa[1][0], ONE2, ONE2);
            mma16816(oc[1][4], pa[1][1], ONE2, ONE2);
        }
        __syncthreads();
    }

    // ---- epilogue: normalize, write fp16 token-major g_Oh[b][n][e] ----
#pragma unroll
    for (int mb = 0; mb < 2; ++mb) {
        const float inv0 = 1.0f / oc[mb][4][0];
        const float inv1 = 1.0f / oc[mb][4][2];
        const int rA = qt * 128 + w * 32 + mb * 16 + g;
        uint16_t* p0 = g_Oh + ((size_t)b * NQ + rA) * CDIM + h * HDIM;
        uint16_t* p1 = p0 + 8 * CDIM;
#pragma unroll
        for (int nbo = 0; nbo < 4; ++nbo) {
            const int d0 = nbo * 8 + 2 * m4;
            *(uint32_t*)(p0 + d0) = h2pack(oc[mb][nbo][0] * inv0, oc[mb][nbo][1] * inv0);
            *(uint32_t*)(p1 + d0) = h2pack(oc[mb][nbo][2] * inv1, oc[mb][nbo][3] * inv1);
        }
    }
}

// =====================================================================
extern "C" void kernel_launch(void* const* d_in, const int* in_sizes, int n_in,
                              void* d_out, int out_size)
{
    const float* x  = (const float*)d_in[0];
    const float* Wq = (const float*)d_in[1];
    const float* bq = (const float*)d_in[2];
    const float* Wk = (const float*)d_in[3];
    const float* bk = (const float*)d_in[4];
    const float* Wv = (const float*)d_in[5];
    const float* bv = (const float*)d_in[6];
    const float* Wo = (const float*)d_in[7];
    const float* bo = (const float*)d_in[8];
    float* out = (float*)d_out;
    (void)in_sizes; (void)n_in; (void)out_size;

    const int qkv_smem = 65536;                   // X 32KB + W 32KB
    const int out_smem = 65536 + 64 * 132 * 4;    // + f32 staging = 99328
    cudaFuncSetAttribute(proj_qkv, cudaFuncAttributeMaxDynamicSharedMemorySize, qkv_smem);
    cudaFuncSetAttribute(proj_out, cudaFuncAttributeMaxDynamicSharedMemorySize, out_smem);

    conv_x<<<dim3(NQ / 64, CDIM / 32, BATCH), 256>>>(x);
    conv_w<<<32, 256>>>(Wq, Wk, Wv, Wo);
    proj_qkv<<<dim3(NQ / 128, BATCH, 3), 256, qkv_smem>>>(bq, bk, bv);
    attn_fa<<<dim3(NQ / 128, NHEAD, BATCH), 128>>>();
    proj_out<<<dim3(NQ / 128, BATCH), 256, out_smem>>>(bo, out);
}